// round 3
// baseline (speedup 1.0000x reference)
#include <cuda_runtime.h>

#define BATCH 1024
#define T     256
#define H     128
#define V     60
#define M     8            // batch rows per CTA
#define WS    132          // padded row stride (floats) -> conflict-free LDS
#define NTHREADS 128
#define NCTA  (BATCH / M)  // 128

typedef unsigned long long u64;

__device__ float g_proj[V * H];   // proj[v][j] = sum_k emb[v][k] * W_ih[j][k]

__device__ __forceinline__ void ffma2(u64& acc, u64 a, u64 b) {
    asm("fma.rn.f32x2 %0, %1, %2, %0;" : "+l"(acc) : "l"(a), "l"(b));
}
__device__ __forceinline__ float2 unpack2(u64 a) {
    float2 r;
    asm("mov.b64 {%0, %1}, %2;" : "=f"(r.x), "=f"(r.y) : "l"(a));
    return r;
}
__device__ __forceinline__ float fast_tanh(float x) {
    // tanh(x) = 1 - 2/(exp(2x)+1); safe at +/-inf of expf
    float e = __expf(2.0f * x);
    return 1.0f - __fdividef(2.0f, e + 1.0f);
}

// ---------------------------------------------------------------------------
// Stage 1: proj[v][j] = emb[v] . W_ih[j]   (60 x 128, trivial)
// ---------------------------------------------------------------------------
__global__ void proj_kernel(const float* __restrict__ emb,
                            const float* __restrict__ W_ih) {
    __shared__ float e[H];
    const int v = blockIdx.x;
    const int j = threadIdx.x;
    e[j] = emb[v * H + j];
    __syncthreads();
    const float* w = W_ih + j * H;
    float s = 0.f;
#pragma unroll 16
    for (int k = 0; k < H; ++k) s += e[k] * w[k];
    g_proj[v * H + j] = s;
}

// ---------------------------------------------------------------------------
// Stage 2: persistent per-CTA recurrence over 256 steps + FC epilogue
// ---------------------------------------------------------------------------
__global__ __launch_bounds__(NTHREADS, 1)
void rnn_kernel(const int* __restrict__ x,
                const int* __restrict__ lengths,
                const float* __restrict__ W_hh,
                const float* __restrict__ W_fc,
                const float* __restrict__ b_fc,
                float* __restrict__ out) {
    extern __shared__ float smem[];
    float* Ws_ = smem;                    // H  * WS
    float* Ps_ = Ws_ + H * WS;            // V  * WS (proj; later reused for W_fc)
    float* Hs_ = Ps_ + V * WS;            // 2 * M * WS (double-buffered hidden)
    float* Ls_ = Hs_ + 2 * M * WS;        // M * WS (hidden at t = len-1)
    int*   Tok = (int*)(Ls_ + M * WS);    // M * T

    const int tid = threadIdx.x;
    const int b0  = blockIdx.x * M;

    // --- load W_hh into padded SMEM ---
    for (int idx = tid; idx < H * (H / 4); idx += NTHREADS) {
        int j = idx >> 5, k4 = idx & 31;
        *(float4*)&Ws_[j * WS + k4 * 4] = *(const float4*)&W_hh[j * H + k4 * 4];
    }
    // --- load proj table ---
    for (int idx = tid; idx < V * (H / 4); idx += NTHREADS) {
        int v = idx >> 5, k4 = idx & 31;
        *(float4*)&Ps_[v * WS + k4 * 4] = *(const float4*)&g_proj[v * H + k4 * 4];
    }
    // --- load tokens for this CTA's 8 rows ---
    for (int idx = tid; idx < M * T; idx += NTHREADS) {
        Tok[idx] = x[b0 * T + idx];
    }
    // --- zero hidden buffers + last buffer (contiguous) ---
    for (int idx = tid; idx < 3 * M * WS; idx += NTHREADS) {
        Hs_[idx] = 0.f;
    }

    // thread decomposition: warp covers 32 j; lane = (mg:2 | jt:3)
    const int warp  = tid >> 5;
    const int lane  = tid & 31;
    const int jt    = lane & 7;          // 8 j-threads
    const int mg    = lane >> 3;         // 4 m-groups
    const int jbase = warp * 32 + jt;    // thread js: jbase + 8*i, i=0..3
    const int m0 = 2 * mg, m1 = 2 * mg + 1;
    const int len0 = lengths[b0 + m0];
    const int len1 = lengths[b0 + m1];

    __syncthreads();

    int cur = 0;
    for (int t = 0; t < T; ++t) {
        const float* Hc = Hs_ + cur * (M * WS);
        float*       Hn = Hs_ + (1 - cur) * (M * WS);

        u64 acc[4][2];
#pragma unroll
        for (int i = 0; i < 4; ++i) { acc[i][0] = 0ull; acc[i][1] = 0ull; }

#pragma unroll 4
        for (int k4 = 0; k4 < 32; ++k4) {
            ulonglong2 h0 = *(const ulonglong2*)&Hc[m0 * WS + k4 * 4];
            ulonglong2 h1 = *(const ulonglong2*)&Hc[m1 * WS + k4 * 4];
#pragma unroll
            for (int i = 0; i < 4; ++i) {
                ulonglong2 w = *(const ulonglong2*)&Ws_[(jbase + 8 * i) * WS + k4 * 4];
                ffma2(acc[i][0], w.x, h0.x);
                ffma2(acc[i][0], w.y, h0.y);
                ffma2(acc[i][1], w.x, h1.x);
                ffma2(acc[i][1], w.y, h1.y);
            }
        }

        const int tk0 = Tok[m0 * T + t];
        const int tk1 = Tok[m1 * T + t];
#pragma unroll
        for (int i = 0; i < 4; ++i) {
            const int j = jbase + 8 * i;
            float2 a0 = unpack2(acc[i][0]);
            float2 a1 = unpack2(acc[i][1]);
            float z0 = a0.x + a0.y + Ps_[tk0 * WS + j];
            float z1 = a1.x + a1.y + Ps_[tk1 * WS + j];
            float h0v = fast_tanh(z0);
            float h1v = fast_tanh(z1);
            Hn[m0 * WS + j] = h0v;
            Hn[m1 * WS + j] = h1v;
            if (t == len0 - 1) Ls_[m0 * WS + j] = h0v;
            if (t == len1 - 1) Ls_[m1 * WS + j] = h1v;
        }
        __syncthreads();
        cur ^= 1;
    }

    // --- FC epilogue: out[b] = last[b] @ W_fc^T + b_fc ---
    // reuse Ps_ for W_fc (proj no longer needed; loop ended with a barrier)
    for (int idx = tid; idx < V * (H / 4); idx += NTHREADS) {
        int v = idx >> 5, k4 = idx & 31;
        *(float4*)&Ps_[v * WS + k4 * 4] = *(const float4*)&W_fc[v * H + k4 * 4];
    }
    __syncthreads();

    for (int p = tid; p < M * V; p += NTHREADS) {
        const int m = p / V, v = p % V;
        const float* lrow = Ls_ + m * WS;
        const float* wrow = Ps_ + v * WS;
        float s = b_fc[v];
#pragma unroll 8
        for (int k = 0; k < H; ++k) s += lrow[k] * wrow[k];
        out[(b0 + m) * V + v] = s;
    }
}

extern "C" void kernel_launch(void* const* d_in, const int* in_sizes, int n_in,
                              void* d_out, int out_size) {
    const int*   x       = (const int*)d_in[0];
    const int*   lengths = (const int*)d_in[1];
    const float* emb     = (const float*)d_in[2];
    const float* W_ih    = (const float*)d_in[3];
    const float* W_hh    = (const float*)d_in[4];
    const float* W_fc    = (const float*)d_in[5];
    const float* b_fc    = (const float*)d_in[6];
    float*       out     = (float*)d_out;

    proj_kernel<<<V, H>>>(emb, W_ih);

    size_t smem = (size_t)(H * WS + V * WS + 2 * M * WS + M * WS) * sizeof(float)
                + (size_t)(M * T) * sizeof(int);
    cudaFuncSetAttribute(rnn_kernel, cudaFuncAttributeMaxDynamicSharedMemorySize,
                         (int)smem);
    rnn_kernel<<<NCTA, NTHREADS, smem>>>(x, lengths, W_hh, W_fc, b_fc, out);
}